// round 12
// baseline (speedup 1.0000x reference)
#include <cuda_runtime.h>
#include <cuda_bf16.h>
#include <cstdint>

#define NN    50000
#define EE    800000
#define D     128
#define DOUTC 64
#define M_TILE 128
#define NTILES ((NN + M_TILE - 1) / M_TILE)   // 391
#define SB_CNT ((NN + 1023) / 1024)           // 49 scan blocks
#define SA    136   // smem row stride in bf16 elements (bank-conflict-free ldmatrix)

// ---------------- scratch (no allocations allowed) ----------------
__device__ int   g_cnt[NN];            // static-zero; re-zeroed by scan_final each run
__device__ int   g_row_ptr[NN + 1];
__device__ int   g_cursor[NN];
__device__ int   g_col[EE];
__device__ int   g_scan[50176];
__device__ int   g_bsum[64];
__device__ __align__(16) float g_B0[(size_t)NN * D];
__device__ __align__(16) float g_B1[(size_t)NN * D];

// ================= helpers =================
__device__ __forceinline__ uint32_t smem_u32(const void* p) {
    uint32_t a;
    asm("{ .reg .u64 t; cvta.to.shared.u64 t, %1; cvt.u32.u64 %0, t; }" : "=r"(a) : "l"(p));
    return a;
}

#define LDSM4(r, addr) \
    asm volatile("ldmatrix.sync.aligned.m8n8.x4.shared.b16 {%0,%1,%2,%3}, [%4];" \
        : "=r"((r)[0]), "=r"((r)[1]), "=r"((r)[2]), "=r"((r)[3]) : "r"(addr))

#define MMA_BF16(c, a, b0, b1) \
    asm volatile("mma.sync.aligned.m16n8k16.row.col.f32.bf16.bf16.f32 " \
        "{%0,%1,%2,%3}, {%4,%5,%6,%7}, {%8,%9}, {%0,%1,%2,%3};" \
        : "+f"((c)[0]), "+f"((c)[1]), "+f"((c)[2]), "+f"((c)[3]) \
        : "r"((a)[0]), "r"((a)[1]), "r"((a)[2]), "r"((a)[3]), "r"(b0), "r"(b1))

__device__ __forceinline__ void split2(float f0, float f1, uint32_t& hi, uint32_t& lo) {
    __nv_bfloat16 h0 = __float2bfloat16_rn(f0);
    __nv_bfloat16 h1 = __float2bfloat16_rn(f1);
    __nv_bfloat16 l0 = __float2bfloat16_rn(f0 - __bfloat162float(h0));
    __nv_bfloat16 l1 = __float2bfloat16_rn(f1 - __bfloat162float(h1));
    hi = (uint32_t)__bfloat16_as_ushort(h0) | ((uint32_t)__bfloat16_as_ushort(h1) << 16);
    lo = (uint32_t)__bfloat16_as_ushort(l0) | ((uint32_t)__bfloat16_as_ushort(l1) << 16);
}

// ---------------- CSR build (4 kernels) ----------------
__global__ void hist_kernel(const int* __restrict__ ei) {
    int e = blockIdx.x * blockDim.x + threadIdx.x;
    if (e < EE) {
        int d = ei[EE + e];
        if (d >= 0 && d < NN) atomicAdd(&g_cnt[d], 1);
    }
}
__global__ void scan_local_kernel() {
    __shared__ int wsum[32];
    int b = blockIdx.x, tid = threadIdx.x;
    int i = b * 1024 + tid;
    int v = (i < NN) ? g_cnt[i] : 0;
    int x = v;
    #pragma unroll
    for (int o = 1; o < 32; o <<= 1) {
        int t = __shfl_up_sync(0xFFFFFFFFu, x, o);
        if ((tid & 31) >= o) x += t;
    }
    if ((tid & 31) == 31) wsum[tid >> 5] = x;
    __syncthreads();
    if (tid < 32) {
        int s = wsum[tid];
        #pragma unroll
        for (int o = 1; o < 32; o <<= 1) {
            int t = __shfl_up_sync(0xFFFFFFFFu, s, o);
            if (tid >= o) s += t;
        }
        wsum[tid] = s;
    }
    __syncthreads();
    int incl = x + ((tid >= 32) ? wsum[(tid >> 5) - 1] : 0);
    g_scan[i] = incl;
    if (tid == 1023) g_bsum[b] = incl;
}
// computes per-block offset inline (redundant 64-wide scan), writes row_ptr/cursor,
// and zeroes g_cnt so the next replay's hist starts clean.
__global__ void scan_final_kernel() {
    __shared__ int sboff;
    __shared__ int w0s;
    int b = blockIdx.x, tid = threadIdx.x;
    if (tid < 64) {
        int v = (tid < SB_CNT) ? g_bsum[tid] : 0;
        int x = v;
        #pragma unroll
        for (int o = 1; o < 32; o <<= 1) {
            int t = __shfl_up_sync(0xFFFFFFFFu, x, o);
            if ((tid & 31) >= o) x += t;
        }
        if (tid == 31) w0s = x;
        __syncwarp();
        if (tid < 32 && tid == b) sboff = x - v;
    }
    __syncthreads();
    if (tid >= 32 && tid < 64 && tid == b) sboff = /* second warp path */ 0;  // placeholder; b<49<64 handled below
    __syncthreads();
    // recompute for b >= 32 (second warp): exclusive prefix = w0s + (scan within warp2) - v
    if (b >= 32 && tid >= 32 && tid < 64) {
        int v = (tid < SB_CNT) ? g_bsum[tid] : 0;
        int x = v;
        #pragma unroll
        for (int o = 1; o < 32; o <<= 1) {
            int t = __shfl_up_sync(0xFFFFFFFFu, x, o);
            if ((tid & 31) >= o) x += t;
        }
        if (tid == b) sboff = w0s + x - v;
    }
    __syncthreads();
    int boff = sboff;
    int i = b * 1024 + tid;
    if (i < NN) {
        int rp = g_scan[i] + boff;
        g_row_ptr[i + 1] = rp;
        g_cursor[i] = rp - g_cnt[i];
        g_cnt[i] = 0;                 // clean for next replay
    }
    if (i == 0) g_row_ptr[0] = 0;
}
__global__ void fill_kernel(const int* __restrict__ ei) {
    int e = blockIdx.x * blockDim.x + threadIdx.x;
    if (e < EE) {
        int d = ei[EE + e];
        int s = ei[e];
        if (d >= 0 && d < NN) {
            int pos = atomicAdd(&g_cursor[d], 1);
            g_col[pos] = s;
        }
    }
}

// ============ split-fp32 GEMM layer via mma.sync bf16 (R6-validated) ============
template <int NT>
__device__ __forceinline__ void gemm_layer(
    const __nv_bfloat16* Ahi, const __nv_bfloat16* Alo,
    const __nv_bfloat16* Bhi, const __nv_bfloat16* Blo,
    int m0, int n0, int lane, float c[2][NT][4])
{
    int arow = m0 + ((lane >> 3) & 1) * 8 + (lane & 7);
    int akc  = (lane >> 4) * 8;
    uint32_t aH = smem_u32(Ahi) + (uint32_t)(arow * SA + akc) * 2;
    uint32_t aL = smem_u32(Alo) + (uint32_t)(arow * SA + akc) * 2;
    int brow = (lane >> 4) * 8 + (lane & 7);
    int bkc  = ((lane >> 3) & 1) * 8;
    uint32_t bH = smem_u32(Bhi) + (uint32_t)bkc * 2;
    uint32_t bL = smem_u32(Blo) + (uint32_t)bkc * 2;

    #pragma unroll
    for (int k0 = 0; k0 < 128; k0 += 16) {
        uint32_t ah0[4], ah1[4], al0[4], al1[4];
        LDSM4(ah0, aH + k0 * 2);
        LDSM4(ah1, aH + (16 * SA + k0) * 2);
        LDSM4(al0, aL + k0 * 2);
        LDSM4(al1, aL + (16 * SA + k0) * 2);
        #pragma unroll
        for (int np = 0; np < NT / 2; np++) {
            uint32_t badd = (uint32_t)((n0 + np * 16 + brow) * SA + k0) * 2;
            uint32_t bh[4], bl[4];
            LDSM4(bh, bH + badd);
            LDSM4(bl, bL + badd);
            MMA_BF16(c[0][np * 2 + 0], ah0, bh[0], bh[1]);
            MMA_BF16(c[0][np * 2 + 0], ah0, bl[0], bl[1]);
            MMA_BF16(c[0][np * 2 + 0], al0, bh[0], bh[1]);
            MMA_BF16(c[1][np * 2 + 0], ah1, bh[0], bh[1]);
            MMA_BF16(c[1][np * 2 + 0], ah1, bl[0], bl[1]);
            MMA_BF16(c[1][np * 2 + 0], al1, bh[0], bh[1]);
            MMA_BF16(c[0][np * 2 + 1], ah0, bh[2], bh[3]);
            MMA_BF16(c[0][np * 2 + 1], ah0, bl[2], bl[3]);
            MMA_BF16(c[0][np * 2 + 1], al0, bh[2], bh[3]);
            MMA_BF16(c[1][np * 2 + 1], ah1, bh[2], bh[3]);
            MMA_BF16(c[1][np * 2 + 1], ah1, bl[2], bl[3]);
            MMA_BF16(c[1][np * 2 + 1], al1, bh[2], bh[3]);
        }
    }
}

// stage W (K x NC row-major, K=128) transposed+split into Bhi/Blo as (n, k)
__device__ __forceinline__ void stage_w(
    const float* __restrict__ w, int NC,
    __nv_bfloat16* Bhi, __nv_bfloat16* Blo, int tid)
{
    for (int i = tid; i < NC * 8; i += 256) {
        int n = i % NC, k0 = (i / NC) * 16;
        uint32_t h[8], l[8];
        #pragma unroll
        for (int j = 0; j < 8; j++) {
            float f0 = w[(k0 + 2 * j)     * NC + n];
            float f1 = w[(k0 + 2 * j + 1) * NC + n];
            split2(f0, f1, h[j], l[j]);
        }
        int off = n * SA + k0;
        *(uint4*)(Bhi + off)     = make_uint4(h[0], h[1], h[2], h[3]);
        *(uint4*)(Bhi + off + 8) = make_uint4(h[4], h[5], h[6], h[7]);
        *(uint4*)(Blo + off)     = make_uint4(l[0], l[1], l[2], l[3]);
        *(uint4*)(Blo + off + 8) = make_uint4(l[4], l[5], l[6], l[7]);
    }
}

// ============ persistent fused (agg +) 2-layer MLP kernel ============
// AGG: stage A = h[r] + sum_{j->r} h[j] via CSR gather. Otherwise direct load.
// layer1: 128->128 relu ; layer2: 128->N2 (+RELU2).
template <int N2, bool RELU2, bool AGG>
__global__ __launch_bounds__(256, 1) void mlp_pers_kernel(
    int src_sel, int dst_sel,
    const float* __restrict__ w1, const float* __restrict__ b1,
    const float* __restrict__ w2, const float* __restrict__ b2,
    const float* __restrict__ xin, float* __restrict__ outp)
{
    extern __shared__ __align__(16) char dyn[];
    __nv_bfloat16* Ahi  = (__nv_bfloat16*)dyn;          // 128*SA
    __nv_bfloat16* Alo  = Ahi  + 128 * SA;
    __nv_bfloat16* B1hi = Alo  + 128 * SA;
    __nv_bfloat16* B1lo = B1hi + 128 * SA;
    __nv_bfloat16* B2hi = B1lo + 128 * SA;
    __nv_bfloat16* B2lo = B2hi + 128 * SA;
    __shared__ float sb1[128];
    __shared__ float sb2[128];

    int tid = threadIdx.x;
    int wid = tid >> 5, lane = tid & 31;
    int m0 = (wid & 3) * 32;

    if (tid < 128) sb1[tid] = b1[tid];
    if (tid < N2)  sb2[tid] = b2[tid];

    stage_w(w1, 128, B1hi, B1lo, tid);
    stage_w(w2, N2,  B2hi, B2lo, tid);

    const float* src = (src_sel == 0) ? xin : (src_sel == 1) ? g_B0 : g_B1;
    const float4* hv = (const float4*)src;
    float* dst = (dst_sel == 0) ? g_B0 : (dst_sel == 1) ? g_B1 : outp;

    for (int tile = blockIdx.x; tile < NTILES; tile += gridDim.x) {
        int row0 = tile * M_TILE;
        __syncthreads();   // prev iter's gemm2 reads of A done; weights ready (iter 0)

        // ---- stage A ----
        if (AGG) {
            // warp-per-row gather: warp wid handles rows [wid*16, wid*16+16)
            int rbase = wid * 16;
            #pragma unroll 1
            for (int rr = 0; rr < 16; rr++) {
                int r = rbase + rr;
                int gr = row0 + r;
                float4 acc = make_float4(0.f, 0.f, 0.f, 0.f);
                if (gr < NN) {
                    acc = hv[(size_t)gr * 32 + lane];
                    int e = g_row_ptr[gr], end = g_row_ptr[gr + 1];
                    for (; e + 4 <= end; e += 4) {
                        int s0 = g_col[e], s1 = g_col[e + 1];
                        int s2 = g_col[e + 2], s3 = g_col[e + 3];
                        float4 v0 = hv[(size_t)s0 * 32 + lane];
                        float4 v1 = hv[(size_t)s1 * 32 + lane];
                        float4 v2 = hv[(size_t)s2 * 32 + lane];
                        float4 v3 = hv[(size_t)s3 * 32 + lane];
                        acc.x += (v0.x + v1.x) + (v2.x + v3.x);
                        acc.y += (v0.y + v1.y) + (v2.y + v3.y);
                        acc.z += (v0.z + v1.z) + (v2.z + v3.z);
                        acc.w += (v0.w + v1.w) + (v2.w + v3.w);
                    }
                    for (; e < end; e++) {
                        int s = g_col[e];
                        float4 v = hv[(size_t)s * 32 + lane];
                        acc.x += v.x; acc.y += v.y; acc.z += v.z; acc.w += v.w;
                    }
                }
                uint32_t h0, l0, h1, l1;
                split2(acc.x, acc.y, h0, l0);
                split2(acc.z, acc.w, h1, l1);
                int off = r * SA + lane * 4;
                *(uint2*)(Ahi + off) = make_uint2(h0, h1);
                *(uint2*)(Alo + off) = make_uint2(l0, l1);
            }
        } else {
            const float4* sv = (const float4*)(src + (size_t)row0 * D);
            for (int i = tid; i < M_TILE * 32; i += 256) {
                int r = i >> 5, c4 = (i & 31) * 4;
                float4 v = make_float4(0.f, 0.f, 0.f, 0.f);
                if (row0 + r < NN) v = sv[i];
                uint32_t h0, l0, h1, l1;
                split2(v.x, v.y, h0, l0);
                split2(v.z, v.w, h1, l1);
                int off = r * SA + c4;
                *(uint2*)(Ahi + off) = make_uint2(h0, h1);
                *(uint2*)(Alo + off) = make_uint2(l0, l1);
            }
        }
        __syncthreads();

        // ---- layer 1: 128 -> 128 ----
        float c1r[2][8][4];
        #pragma unroll
        for (int a = 0; a < 2; a++)
            #pragma unroll
            for (int b = 0; b < 8; b++)
                #pragma unroll
                for (int q = 0; q < 4; q++) c1r[a][b][q] = 0.f;
        int n0 = (wid >> 2) * 64;
        gemm_layer<8>(Ahi, Alo, B1hi, B1lo, m0, n0, lane, c1r);
        __syncthreads();   // all gemm1 reads of A done before epi1 overwrites

        // epilogue 1: bias+relu, re-split into Ahi/Alo
        {
            int gid = lane >> 2, qid = lane & 3;
            #pragma unroll
            for (int mt = 0; mt < 2; mt++)
                #pragma unroll
                for (int nt = 0; nt < 8; nt++) {
                    int cb = n0 + nt * 8 + qid * 2;
                    int r0 = m0 + mt * 16 + gid;
                    float f0 = fmaxf(c1r[mt][nt][0] + sb1[cb], 0.f);
                    float f1 = fmaxf(c1r[mt][nt][1] + sb1[cb + 1], 0.f);
                    uint32_t hi, lo;
                    split2(f0, f1, hi, lo);
                    *(uint32_t*)(Ahi + r0 * SA + cb) = hi;
                    *(uint32_t*)(Alo + r0 * SA + cb) = lo;
                    float f2 = fmaxf(c1r[mt][nt][2] + sb1[cb], 0.f);
                    float f3 = fmaxf(c1r[mt][nt][3] + sb1[cb + 1], 0.f);
                    split2(f2, f3, hi, lo);
                    *(uint32_t*)(Ahi + (r0 + 8) * SA + cb) = hi;
                    *(uint32_t*)(Alo + (r0 + 8) * SA + cb) = lo;
                }
        }
        __syncthreads();

        // ---- layer 2: 128 -> N2 ----
        constexpr int NT2 = N2 / 16;
        float c2r[2][NT2][4];
        #pragma unroll
        for (int a = 0; a < 2; a++)
            #pragma unroll
            for (int b = 0; b < NT2; b++)
                #pragma unroll
                for (int q = 0; q < 4; q++) c2r[a][b][q] = 0.f;
        int n02 = (wid >> 2) * (N2 / 2);
        gemm_layer<NT2>(Ahi, Alo, B2hi, B2lo, m0, n02, lane, c2r);

        // epilogue 2: bias (+relu) -> global
        {
            int gid = lane >> 2, qid = lane & 3;
            #pragma unroll
            for (int mt = 0; mt < 2; mt++)
                #pragma unroll
                for (int nt = 0; nt < NT2; nt++) {
                    int cb = n02 + nt * 8 + qid * 2;
                    int r0 = m0 + mt * 16 + gid;
                    float f0 = c2r[mt][nt][0] + sb2[cb];
                    float f1 = c2r[mt][nt][1] + sb2[cb + 1];
                    float f2 = c2r[mt][nt][2] + sb2[cb];
                    float f3 = c2r[mt][nt][3] + sb2[cb + 1];
                    if (RELU2) {
                        f0 = fmaxf(f0, 0.f); f1 = fmaxf(f1, 0.f);
                        f2 = fmaxf(f2, 0.f); f3 = fmaxf(f3, 0.f);
                    }
                    int gr0 = row0 + r0;
                    if (gr0 < NN)
                        *(float2*)(dst + (size_t)gr0 * N2 + cb) = make_float2(f0, f1);
                    if (gr0 + 8 < NN)
                        *(float2*)(dst + (size_t)(gr0 + 8) * N2 + cb) = make_float2(f2, f3);
                }
        }
    }
}

// ---------------- launch ----------------
extern "C" void kernel_launch(void* const* d_in, const int* in_sizes, int n_in,
                              void* d_out, int out_size) {
    const float* x  = (const float*)d_in[0];
    const int*   ei = (const int*)d_in[1];     // int32 (JAX x64 disabled)
    const float* c1w1 = (const float*)d_in[2];
    const float* c1b1 = (const float*)d_in[3];
    const float* c1w2 = (const float*)d_in[4];
    const float* c1b2 = (const float*)d_in[5];
    const float* c2w1 = (const float*)d_in[6];
    const float* c2b1 = (const float*)d_in[7];
    const float* c2w2 = (const float*)d_in[8];
    const float* c2b2 = (const float*)d_in[9];
    const float* c3w1 = (const float*)d_in[10];
    const float* c3b1 = (const float*)d_in[11];
    const float* c3w2 = (const float*)d_in[12];
    const float* c3b2 = (const float*)d_in[13];
    const float* l1w  = (const float*)d_in[14];
    const float* l1b  = (const float*)d_in[15];
    const float* l2w  = (const float*)d_in[16];
    const float* l2b  = (const float*)d_in[17];
    float* out = (float*)d_out;

    const int MLP_SMEM = 6 * 128 * SA * 2;   // 208896 bytes
    cudaFuncSetAttribute(mlp_pers_kernel<128, true, true>,
                         cudaFuncAttributeMaxDynamicSharedMemorySize, MLP_SMEM);
    cudaFuncSetAttribute(mlp_pers_kernel<64, false, false>,
                         cudaFuncAttributeMaxDynamicSharedMemorySize, MLP_SMEM);

    // CSR build: 4 kernels (zeroing folded into scan_final; boff inline)
    hist_kernel<<<(EE + 255) / 256, 256>>>(ei);
    scan_local_kernel<<<SB_CNT, 1024>>>();
    scan_final_kernel<<<SB_CNT, 1024>>>();
    fill_kernel<<<(EE + 255) / 256, 256>>>(ei);

    const int PERS_BLOCKS = 148;   // one CTA per SM (persistent)

    // conv1: fused agg(x)+mlp -> B0
    mlp_pers_kernel<128, true, true><<<PERS_BLOCKS, 256, MLP_SMEM>>>(
        0, 0, c1w1, c1b1, c1w2, c1b2, x, out);
    // conv2: fused agg(B0)+mlp -> B1
    mlp_pers_kernel<128, true, true><<<PERS_BLOCKS, 256, MLP_SMEM>>>(
        1, 1, c2w1, c2b1, c2w2, c2b2, x, out);
    // conv3: fused agg(B1)+mlp -> B0
    mlp_pers_kernel<128, true, true><<<PERS_BLOCKS, 256, MLP_SMEM>>>(
        2, 0, c3w1, c3b1, c3w2, c3b2, x, out);
    // head: B0 -> out (no aggregation)
    mlp_pers_kernel<64, false, false><<<PERS_BLOCKS, 256, MLP_SMEM>>>(
        1, 2, l1w, l1b, l2w, l2b, x, out);
}